// round 16
// baseline (speedup 1.0000x reference)
#include <cuda_runtime.h>
#include <cuda_fp16.h>
#include <math.h>
#include <stdint.h>

#define Bb 2
#define Tt 2048
#define Dd 2048
#define NQ 16
#define NK 8
#define HD 128
#define MROWS (Bb * Tt)

// Scratch (device globals: allocation-free rule)
__device__ __half g_xh[(size_t)MROWS * Dd];         // half x
__device__ __half g_qh[(size_t)MROWS * NQ * HD];    // half Q (post rms+rope)
__device__ __half g_kh[(size_t)MROWS * NK * HD];    // half K (post rms+rope)
__device__ __half g_vt[(size_t)Bb * NK * HD * Tt];  // half V^T [b][kh][h][t]
__device__ __half g_oh[(size_t)MROWS * NQ * HD];    // half attention output
__device__ __half g_wqkv[4096 * 2048];              // [q_w^T; k_w^T; v_w^T]
__device__ __half g_wto[2048 * 2048];               // o_w^T [D][NH]
__device__ float  g_sin[Tt * 64];
__device__ float  g_cos[Tt * 64];

__device__ __forceinline__ uint32_t pack2(float a, float b) {
    __half2 h = __floats2half2_rn(a, b);
    return *(uint32_t*)&h;
}

__device__ __forceinline__ void mma_f16(float* d, const uint32_t* a,
                                        uint32_t b0, uint32_t b1) {
    asm volatile(
        "mma.sync.aligned.m16n8k16.row.col.f32.f16.f16.f32 "
        "{%0,%1,%2,%3}, {%4,%5,%6,%7}, {%8,%9}, {%0,%1,%2,%3};"
        : "+f"(d[0]), "+f"(d[1]), "+f"(d[2]), "+f"(d[3])
        : "r"(a[0]), "r"(a[1]), "r"(a[2]), "r"(a[3]), "r"(b0), "r"(b1));
}

__device__ __forceinline__ void ldsm4h(uint32_t* r, const __half* p) {
    uint32_t a = (uint32_t)__cvta_generic_to_shared(p);
    asm volatile("ldmatrix.sync.aligned.m8n8.x4.shared.b16 {%0,%1,%2,%3}, [%4];"
                 : "=r"(r[0]), "=r"(r[1]), "=r"(r[2]), "=r"(r[3]) : "r"(a));
}

__device__ __forceinline__ void cpa16(void* dst, const void* src) {
    uint32_t d = (uint32_t)__cvta_generic_to_shared(dst);
    asm volatile("cp.async.cg.shared.global [%0], [%1], 16;" :: "r"(d), "l"(src));
}
#define CP_COMMIT asm volatile("cp.async.commit_group;")
#define CP_WAIT(n) asm volatile("cp.async.wait_group %0;" :: "n"(n))

// ---------------------------------------------------------------------------
// Combined prep: blocks [0,4096) convert x fp32->half (8 elems/thread);
// blocks [4096, 4608) fill the RoPE sin/cos table.
// ---------------------------------------------------------------------------
__global__ __launch_bounds__(256) void prep(const float* __restrict__ x,
                                            __half* __restrict__ xh) {
    if (blockIdx.x < 4096) {
        size_t i = ((size_t)blockIdx.x * 256 + threadIdx.x) * 8;
        float4 a = *(const float4*)(x + i);
        float4 b = *(const float4*)(x + i + 4);
        uint4 w = make_uint4(pack2(a.x, a.y), pack2(a.z, a.w),
                             pack2(b.x, b.y), pack2(b.z, b.w));
        *(uint4*)(xh + i) = w;
    } else {
        int idx = (blockIdx.x - 4096) * 256 + threadIdx.x;
        if (idx >= Tt * 64) return;
        int t = idx >> 6, i = idx & 63;
        double ang = (double)t * exp(-0.21586735246819178 * (double)i);
        double s, c;
        sincos(ang, &s, &c);
        g_sin[idx] = (float)s;
        g_cos[idx] = (float)c;
    }
}

// ---------------------------------------------------------------------------
// Fused q/k/v weight transpose into g_wqkv [4096][2048] half.
// ---------------------------------------------------------------------------
__global__ __launch_bounds__(256) void transpose_qkv(const float* __restrict__ qw,
                                                     const float* __restrict__ kw,
                                                     const float* __restrict__ vw,
                                                     __half* __restrict__ out) {
    __shared__ float t[32][33];
    const int colg = blockIdx.x << 5;
    const int by = blockIdx.y << 5;
    const float* src;
    int srccol, C;
    if (colg < 2048)      { src = qw; srccol = colg;        C = 2048; }
    else if (colg < 3072) { src = kw; srccol = colg - 2048; C = 1024; }
    else                  { src = vw; srccol = colg - 3072; C = 1024; }
    const int tx = threadIdx.x & 31, ty = threadIdx.x >> 5;
#pragma unroll
    for (int i = 0; i < 32; i += 8)
        t[ty + i][tx] = src[(size_t)(by + ty + i) * C + srccol + tx];
    __syncthreads();
#pragma unroll
    for (int i = 0; i < 32; i += 8)
        out[(size_t)(colg + ty + i) * 2048 + by + tx] = __float2half(t[tx][ty + i]);
}

// ---------------------------------------------------------------------------
// fp32 -> half transpose for o_w
// ---------------------------------------------------------------------------
__global__ __launch_bounds__(256) void transpose_h(const float* __restrict__ in,
                                                   __half* __restrict__ out,
                                                   int R, int C) {
    __shared__ float t[32][33];
    const int bx = blockIdx.x << 5, by = blockIdx.y << 5;
    const int tx = threadIdx.x & 31, ty = threadIdx.x >> 5;
#pragma unroll
    for (int i = 0; i < 32; i += 8)
        t[ty + i][tx] = in[(size_t)(by + ty + i) * C + bx + tx];
    __syncthreads();
#pragma unroll
    for (int i = 0; i < 32; i += 8)
        out[(size_t)(bx + ty + i) * R + by + tx] = __float2half(t[tx][ty + i]);
}

// ---------------------------------------------------------------------------
// fp16 GEMM, 3-stage cp.async ring + double-buffered mma fragments.
// Per iteration: ldsm(ks1) | mma(ks0) | wait/bar/stage | ldsm(next ks0) |
// mma(ks1) -- every mma burst overlaps the other buffer's ldmatrix.
// Block 128x128x32, 8 warps (2m x 4n), __launch_bounds__(256,2).
// MODE 0: fp32 row-major out C0. MODE 1: fused QKV epilogue.
// ---------------------------------------------------------------------------
template <int MODE>
__global__ __launch_bounds__(256, 2) void gemm_h6(const __half* __restrict__ A,
                                                  const __half* __restrict__ BT,
                                                  float* __restrict__ C0,
                                                  __half* __restrict__ Qh,
                                                  __half* __restrict__ Kh,
                                                  __half* __restrict__ Vt,
                                                  const float* __restrict__ qnw,
                                                  const float* __restrict__ knw,
                                                  int M, int N, int K) {
    extern __shared__ __half sm3[];
    __half* sA = sm3;             // 3 * 5120
    __half* sB = sm3 + 3 * 5120;  // 3 * 5120

    const int tid = threadIdx.x;
    const int bm = blockIdx.y << 7, bn = blockIdx.x << 7;
    const int warp = tid >> 5, lane = tid & 31;
    const int wm = (warp >> 2) << 6, wn = (warp & 3) << 5;
    const int grp = lane >> 2, qd = lane & 3;

    const int rs = tid >> 1;
    const int cb = (tid & 1) << 4;

    const int a_row = (lane & 7) + ((lane >> 3) & 1) * 8;
    const int a_col = ((lane >> 4) & 1) * 8;
    const int b_row = (lane & 7) + ((lane >> 4) & 1) * 8;
    const int b_col = ((lane >> 3) & 1) * 8;

    float acc[4][4][4];
#pragma unroll
    for (int i = 0; i < 4; i++)
#pragma unroll
        for (int j = 0; j < 4; j++)
#pragma unroll
            for (int r = 0; r < 4; r++) acc[i][j][r] = 0.f;

    const __half* Ap = A + (size_t)(bm + rs) * K + cb;
    const __half* Bp = BT + (size_t)(bn + rs) * K + cb;
    const int soff = rs * 40 + cb;

    const int nkt = K >> 5;

    // prologue: stage tiles 0,1,2 into slots 0,1,2
#pragma unroll
    for (int s = 0; s < 3; s++) {
        const int k0 = s << 5;
        cpa16(&sA[s * 5120 + soff], Ap + k0);
        cpa16(&sA[s * 5120 + soff + 8], Ap + k0 + 8);
        cpa16(&sB[s * 5120 + soff], Bp + k0);
        cpa16(&sB[s * 5120 + soff + 8], Bp + k0 + 8);
        CP_COMMIT;
    }
    CP_WAIT(2);      // tile 0 complete
    __syncthreads();

    uint32_t Fa0[4][4], Fb0[2][4], Fa1[4][4], Fb1[2][4];

    // preload fragments (tile 0, ks=0)
#pragma unroll
    for (int mt = 0; mt < 4; mt++)
        ldsm4h(Fa0[mt], &sA[(wm + mt * 16 + a_row) * 40 + a_col]);
#pragma unroll
    for (int np = 0; np < 2; np++)
        ldsm4h(Fb0[np], &sB[(wn + np * 16 + b_row) * 40 + b_col]);

    int slot = 0;
    for (int kt = 0; kt < nkt; kt++) {
        const __half* sAb = sA + slot * 5120;
        const __half* sBb = sB + slot * 5120;

        // ldsm ks=1 of current tile (overlaps mma below)
#pragma unroll
        for (int mt = 0; mt < 4; mt++)
            ldsm4h(Fa1[mt], &sAb[(wm + mt * 16 + a_row) * 40 + 16 + a_col]);
#pragma unroll
        for (int np = 0; np < 2; np++)
            ldsm4h(Fb1[np], &sBb[(wn + np * 16 + b_row) * 40 + 16 + b_col]);

        // mma ks=0
#pragma unroll
        for (int mt = 0; mt < 4; mt++)
#pragma unroll
            for (int nt = 0; nt < 4; nt++)
                mma_f16(acc[mt][nt], Fa0[mt],
                        Fb0[nt >> 1][(nt & 1) * 2], Fb0[nt >> 1][(nt & 1) * 2 + 1]);

        CP_WAIT(1);         // tile kt+1 complete
        __syncthreads();    // all reads of slot (kt) done; safe to re-stage it
        if (kt + 3 < nkt) {
            const int k0 = (kt + 3) << 5;
            cpa16(&sA[slot * 5120 + soff], Ap + k0);
            cpa16(&sA[slot * 5120 + soff + 8], Ap + k0 + 8);
            cpa16(&sB[slot * 5120 + soff], Bp + k0);
            cpa16(&sB[slot * 5120 + soff + 8], Bp + k0 + 8);
        }
        CP_COMMIT;

        const int ns = (slot + 1 >= 3) ? 0 : slot + 1;
        if (kt + 1 < nkt) {
            const __half* sAn = sA + ns * 5120;
            const __half* sBn = sB + ns * 5120;
            // ldsm ks=0 of next tile (overlaps mma below)
#pragma unroll
            for (int mt = 0; mt < 4; mt++)
                ldsm4h(Fa0[mt], &sAn[(wm + mt * 16 + a_row) * 40 + a_col]);
#pragma unroll
            for (int np = 0; np < 2; np++)
                ldsm4h(Fb0[np], &sBn[(wn + np * 16 + b_row) * 40 + b_col]);
        }

        // mma ks=1
#pragma unroll
        for (int mt = 0; mt < 4; mt++)
#pragma unroll
            for (int nt = 0; nt < 4; nt++)
                mma_f16(acc[mt][nt], Fa1[mt],
                        Fb1[nt >> 1][(nt & 1) * 2], Fb1[nt >> 1][(nt & 1) * 2 + 1]);

        slot = ns;
    }

    if (MODE == 0) {
#pragma unroll
        for (int mt = 0; mt < 4; mt++)
#pragma unroll
            for (int nt = 0; nt < 4; nt++) {
                int row = bm + wm + (mt << 4) + grp;
                int col = bn + wn + (nt << 3) + (qd << 1);
                *(float2*)(C0 + (size_t)row * N + col) =
                    make_float2(acc[mt][nt][0], acc[mt][nt][1]);
                *(float2*)(C0 + (size_t)(row + 8) * N + col) =
                    make_float2(acc[mt][nt][2], acc[mt][nt][3]);
            }
    } else if (bn >= 3072) {
        // V region: half, transposed into [b][kh*HD+h][t]
#pragma unroll
        for (int mt = 0; mt < 4; mt++)
#pragma unroll
            for (int nt = 0; nt < 4; nt++) {
                int row = bm + wm + (mt << 4) + grp;
                int col = (bn - 3072) + wn + (nt << 3) + (qd << 1);
                int b = row >> 11, t = row & 2047;
                size_t base0 = ((size_t)b * NK * HD + col) * Tt + t;
                size_t base1 = ((size_t)b * NK * HD + col + 1) * Tt + t;
                Vt[base0] = __float2half(acc[mt][nt][0]);
                Vt[base1] = __float2half(acc[mt][nt][1]);
                Vt[base0 + 8] = __float2half(acc[mt][nt][2]);
                Vt[base1 + 8] = __float2half(acc[mt][nt][3]);
            }
    } else {
        // Q/K region: fused RMSNorm + RoPE via fp32 smem ytile.
        __syncthreads();
        float* yt = (float*)sm3;  // 128 x 132 fp32 = 67584 B
#pragma unroll
        for (int mt = 0; mt < 4; mt++)
#pragma unroll
            for (int nt = 0; nt < 4; nt++) {
                int row = wm + (mt << 4) + grp;
                int col = wn + (nt << 3) + (qd << 1);
                yt[row * 132 + col] = acc[mt][nt][0];
                yt[row * 132 + col + 1] = acc[mt][nt][1];
                yt[(row + 8) * 132 + col] = acc[mt][nt][2];
                yt[(row + 8) * 132 + col + 1] = acc[mt][nt][3];
            }
        __syncthreads();

        const float* wvec = (bn < 2048) ? qnw : knw;
        const int row = tid >> 1, hf = tid & 1;
        const float* yr = yt + row * 132;

        float ss = 0.f;
#pragma unroll
        for (int c = 0; c < 64; c += 4) {
            float4 v = *(const float4*)(yr + hf * 64 + c);
            ss += v.x * v.x + v.y * v.y + v.z * v.z + v.w * v.w;
        }
        ss += __shfl_xor_sync(0xffffffffu, ss, 1);
        const float rinv = rsqrtf(ss * (1.0f / (float)HD) + 1e-6f);

        const int grow = bm + row;
        const int b = grow >> 11, t = grow & 2047;
        __half* dst;
        if (bn < 2048) dst = Qh + ((size_t)(b * Tt + t) * NQ + (bn >> 7)) * HD;
        else           dst = Kh + ((size_t)(b * Tt + t) * NK + ((bn - 2048) >> 7)) * HD;
        const float* srow = g_sin + t * 64;
        const float* crow = g_cos + t * 64;

#pragma unroll
        for (int c0 = 0; c0 < 64; c0 += 4) {
            const int c = hf * 64 + c0;
            float4 yv = *(const float4*)(yr + c);
            float4 pv = *(const float4*)(yr + (c ^ 64));
            float4 wv = *(const float4*)(wvec + c);
            float4 wp = *(const float4*)(wvec + (c ^ 64));
            float4 sv = *(const float4*)(srow + c0);
            float4 cv = *(const float4*)(crow + c0);
            float y0 = wv.x * yv.x * rinv, p0 = wp.x * pv.x * rinv;
            float y1 = wv.y * yv.y * rinv, p1 = wp.y * pv.y * rinv;
            float y2 = wv.z * yv.z * rinv, p2 = wp.z * pv.z * rinv;
            float y3 = wv.w * yv.w * rinv, p3 = wp.w * pv.w * rinv;
            float o0, o1, o2, o3;
            if (hf == 0) {
                o0 = y0 * cv.x - p0 * sv.x; o1 = y1 * cv.y - p1 * sv.y;
                o2 = y2 * cv.z - p2 * sv.z; o3 = y3 * cv.w - p3 * sv.w;
            } else {
                o0 = y0 * cv.x + p0 * sv.x; o1 = y1 * cv.y + p1 * sv.y;
                o2 = y2 * cv.z + p2 * sv.z; o3 = y3 * cv.w + p3 * sv.w;
            }
            *(uint2*)(dst + c) = make_uint2(pack2(o0, o1), pack2(o2, o3));
        }
    }
}

// ---------------------------------------------------------------------------
// Flash attention fp16 mma.sync, s-tile 64, cp.async double-buffered K/V.
// ---------------------------------------------------------------------------
__global__ __launch_bounds__(256) void flash_h2(const __half* __restrict__ Q,
                                                const __half* __restrict__ Kc,
                                                const __half* __restrict__ VT,
                                                __half* __restrict__ O) {
    extern __shared__ __half smh[];
    __half* sK = smh;                  // 2 * 8704
    __half* sVT = sK + 2 * 8704;       // 2 * 9216
    __half* sP = sVT + 2 * 9216;       // 8 * 1152

    const int tid = threadIdx.x;
    const int w = tid >> 5, lane = tid & 31;
    const int grp = lane >> 2, qd = lane & 3;
    const int b = blockIdx.z, n = blockIdx.y;
    const int qt = blockIdx.x << 7;
    const int kh = n >> 1;

    const int a_row = (lane & 7) + ((lane >> 3) & 1) * 8;
    const int a_col = ((lane >> 4) & 1) * 8;
    const int b_row = (lane & 7) + ((lane >> 4) & 1) * 8;
    const int b_col = ((lane >> 3) & 1) * 8;

    uint32_t qf[8][4];
    {
        const __half* Qb = Q + ((size_t)(b * Tt + qt) * NQ + n) * HD;
#pragma unroll
        for (int c = 0; c < 2; c++) {
            __half* sKc = sK + c * 8704;
#pragma unroll
            for (int u = 0; u < 4; u++) {
                int cc = tid + (u << 8);
                int r = cc >> 4, ch = (cc & 15) << 3;
                *(uint4*)&sKc[r * 136 + ch] =
                    *(const uint4*)(Qb + (size_t)(c * 64 + r) * (NQ * HD) + ch);
            }
            __syncthreads();
            if ((w >> 2) == c) {
                const int lr = ((w & 3) << 4) + a_row;
#pragma unroll
                for (int kp = 0; kp < 8; kp++)
                    ldsm4h(qf[kp], &sKc[lr * 136 + (kp << 4) + a_col]);
            }
            __syncthreads();
        }
    }

    float oacc[16][4];
#pragma unroll
    for (int i = 0; i < 16; i++)
#pragma unroll
        for (int j = 0; j < 4; j++) oacc[i][j] = 0.f;
    float m0 = -1e30f, m1 = -1e30f, l0 = 0.f, l1 = 0.f;

    const float scale = 0.08838834764831845f;
    const int row0 = qt + (w << 4) + grp;
    const int row1 = row0 + 8;
    const int wmax = qt + (w << 4) + 15;
    const int ntile = (qt >> 6) + 2;
    __half* sPw = sP + w * 1152;

    const __half* Kbase = Kc + ((size_t)b * Tt * NK + kh) * HD;
    const __half* Vbase = VT + ((size_t)(b * NK + kh) * HD) * Tt;

    auto stage = [&](int st, int buf) {
        const __half* Kb = Kbase + (size_t)(st << 6) * (NK * HD);
        const __half* Vb = Vbase + (st << 6);
        __half* dK = sK + buf * 8704;
        __half* dV = sVT + buf * 9216;
#pragma unroll
        for (int u = 0; u < 4; u++) {
            int cc = tid + (u << 8);
            int r = cc >> 4, ch = (cc & 15) << 3;
            cpa16(&dK[r * 136 + ch], Kb + (size_t)r * (NK * HD) + ch);
            int rv = cc >> 3, cv = (cc & 7) << 3;
            cpa16(&dV[rv * 72 + cv], Vb + (size_t)rv * Tt + cv);
        }
    };

    stage(0, 0);
    CP_COMMIT;

    for (int st = 0; st < ntile; st++) {
        const int s0 = st << 6;
        const int buf = st & 1;
        if (st + 1 < ntile) {
            stage(st + 1, buf ^ 1);
            CP_COMMIT;
            CP_WAIT(1);
        } else {
            CP_WAIT(0);
        }
        __syncthreads();

        if (s0 <= wmax) {
            const __half* sKb = sK + buf * 8704;
            const __half* sVb = sVT + buf * 9216;

            float sacc[8][4];
#pragma unroll
            for (int i = 0; i < 8; i++)
#pragma unroll
                for (int j = 0; j < 4; j++) sacc[i][j] = 0.f;
#pragma unroll
            for (int kp = 0; kp < 8; kp++) {
#pragma unroll
                for (int np = 0; np < 4; np++) {
                    uint32_t bf[4];
                    ldsm4h(bf, &sKb[(np * 16 + b_row) * 136 + (kp << 4) + b_col]);
                    mma_f16(sacc[np * 2], qf[kp], bf[0], bf[1]);
                    mma_f16(sacc[np * 2 + 1], qf[kp], bf[2], bf[3]);
                }
            }

            float mx0 = -1e30f, mx1 = -1e30f;
#pragma unroll
            for (int nt = 0; nt < 8; nt++) {
                int colb = s0 + (nt << 3) + (qd << 1);
                float v0 = sacc[nt][0] * scale;
                float v1 = sacc[nt][1] * scale;
                float v2 = sacc[nt][2] * scale;
                float v3 = sacc[nt][3] * scale;
                if (colb > row0)     v0 = -1e30f;
                if (colb + 1 > row0) v1 = -1e30f;
                if (colb > row1)     v2 = -1e30f;
                if (colb + 1 > row1) v3 = -1e30f;
                sacc[nt][0] = v0; sacc[nt][1] = v1; sacc[nt][2] = v2; sacc[nt][3] = v3;
                mx0 = fmaxf(mx0, fmaxf(v0, v1));
                mx1 = fmaxf(mx1, fmaxf(v2, v3));
            }
            mx0 = fmaxf(mx0, __shfl_xor_sync(0xffffffffu, mx0, 1));
            mx0 = fmaxf(mx0, __shfl_xor_sync(0xffffffffu, mx0, 2));
            mx1 = fmaxf(mx1, __shfl_xor_sync(0xffffffffu, mx1, 1));
            mx1 = fmaxf(mx1, __shfl_xor_sync(0xffffffffu, mx1, 2));
            float mn0 = fmaxf(m0, mx0), mn1 = fmaxf(m1, mx1);
            float a0 = __expf(m0 - mn0), a1 = __expf(m1 - mn1);
            m0 = mn0; m1 = mn1;
            float ps0 = 0.f, ps1 = 0.f;
#pragma unroll
            for (int nt = 0; nt < 8; nt++) {
                float p0 = __expf(sacc[nt][0] - m0);
                float p1 = __expf(sacc[nt][1] - m0);
                float p2 = __expf(sacc[nt][2] - m1);
                float p3 = __expf(sacc[nt][3] - m1);
                ps0 += p0 + p1; ps1 += p2 + p3;
                int col = (nt << 3) + (qd << 1);
                *(uint32_t*)&sPw[grp * 72 + col] = pack2(p0, p1);
                *(uint32_t*)&sPw[(grp + 8) * 72 + col] = pack2(p2, p3);
            }
            ps0 += __shfl_xor_sync(0xffffffffu, ps0, 1);
            ps0 += __shfl_xor_sync(0xffffffffu, ps0, 2);
            ps1 += __shfl_xor_sync(0xffffffffu, ps1, 1);
            ps1 += __shfl_xor_sync(0xffffffffu, ps1, 2);
            l0 = l0 * a0 + ps0;
            l1 = l1 * a1 + ps1;
#pragma unroll
            for (int nt = 0; nt < 16; nt++) {
                oacc[nt][0] *= a0; oacc[nt][1] *= a0;
                oacc[nt][2] *= a1; oacc[nt][3] *= a1;
            }
            __syncwarp();

#pragma unroll
            for (int kp = 0; kp < 4; kp++) {
                uint32_t af[4];
                ldsm4h(af, &sPw[a_row * 72 + (kp << 4) + a_col]);
#pragma unroll
                for (int np = 0; np < 8; np++) {
                    uint32_t bf[4];
                    ldsm4h(bf, &sVb[(np * 16 + b_row) * 72 + (kp << 4) + b_col]);
                    mma_f16(oacc[np * 2], af, bf[0], bf[1]);
                    mma_f16(oacc[np * 2 + 1], af, bf[2], bf[3]);
                }
            }
        }
        __syncthreads();
    }

    const float i0 = 1.0f / l0, i1 = 1.0f / l1;
    __half* Ob0 = O + ((size_t)(b * Tt + row0) * NQ + n) * HD;
    __half* Ob1 = O + ((size_t)(b * Tt + row1) * NQ + n) * HD;
#pragma unroll
    for (int nt = 0; nt < 16; nt++) {
        int col = (nt << 3) + (qd << 1);
        *(uint32_t*)(Ob0 + col) = pack2(oacc[nt][0] * i0, oacc[nt][1] * i0);
        *(uint32_t*)(Ob1 + col) = pack2(oacc[nt][2] * i1, oacc[nt][3] * i1);
    }
}

// ---------------------------------------------------------------------------
// Launch (launch #4 = flash_h2, profiled by ncu)
// ---------------------------------------------------------------------------
extern "C" void kernel_launch(void* const* d_in, const int* in_sizes, int n_in,
                              void* d_out, int out_size) {
    (void)in_sizes; (void)n_in; (void)out_size;
    const float* x   = (const float*)d_in[0];
    const float* qw  = (const float*)d_in[1];
    const float* kw  = (const float*)d_in[2];
    const float* vw  = (const float*)d_in[3];
    const float* ow  = (const float*)d_in[4];
    const float* qnw = (const float*)d_in[5];
    const float* knw = (const float*)d_in[6];
    float* out = (float*)d_out;

    __half *gxh, *gqh, *gkh, *gvt, *goh, *wqkv, *wto;
    cudaGetSymbolAddress((void**)&gxh, g_xh);
    cudaGetSymbolAddress((void**)&gqh, g_qh);
    cudaGetSymbolAddress((void**)&gkh, g_kh);
    cudaGetSymbolAddress((void**)&gvt, g_vt);
    cudaGetSymbolAddress((void**)&goh, g_oh);
    cudaGetSymbolAddress((void**)&wqkv, g_wqkv);
    cudaGetSymbolAddress((void**)&wto, g_wto);

    const int M = MROWS;     // 4096
    const int NH = NQ * HD;  // 2048

    cudaFuncSetAttribute(gemm_h6<0>, cudaFuncAttributeMaxDynamicSharedMemorySize, 61440);
    cudaFuncSetAttribute(gemm_h6<1>, cudaFuncAttributeMaxDynamicSharedMemorySize, 67584);

    // 1: prep (x->half + rope table)
    prep<<<4096 + 512, 256>>>(x, gxh);
    // 2: fused qkv weight transpose
    transpose_qkv<<<dim3(128, 64), 256>>>(qw, kw, vw, wqkv);
    // 3: fused QKV projection + rms + rope + V-transpose
    gemm_h6<1><<<dim3(32, 32), 256, 67584>>>(gxh, wqkv, nullptr, gqh, gkh, gvt,
                                             qnw, knw, M, 4096, Dd);
    // 4: flash attention (profiled)
    size_t fsmem = (size_t)(2 * 8704 + 2 * 9216 + 8 * 1152) * sizeof(__half); // 90112
    cudaFuncSetAttribute(flash_h2, cudaFuncAttributeMaxDynamicSharedMemorySize, (int)fsmem);
    flash_h2<<<dim3(Tt / 128, NQ, Bb), 256, fsmem>>>(gqh, gkh, gvt, goh);
    // 5: o_w transpose
    transpose_h<<<dim3(Dd / 32, NH / 32), 256>>>(ow, wto, NH, Dd);
    // 6: output projection
    gemm_h6<0><<<dim3(Dd / 128, M / 128), 256, 61440>>>(goh, wto, out, nullptr, nullptr,
                                                        nullptr, nullptr, nullptr, M, Dd, NH);
}

// round 17
// speedup vs baseline: 1.0401x; 1.0401x over previous
#include <cuda_runtime.h>
#include <cuda_fp16.h>
#include <math.h>
#include <stdint.h>

#define Bb 2
#define Tt 2048
#define Dd 2048
#define NQ 16
#define NK 8
#define HD 128
#define MROWS (Bb * Tt)

// Scratch (device globals: allocation-free rule)
__device__ __half g_xh[(size_t)MROWS * Dd];         // half x
__device__ __half g_qh[(size_t)MROWS * NQ * HD];    // half Q (post rms+rope)
__device__ __half g_kh[(size_t)MROWS * NK * HD];    // half K (post rms+rope)
__device__ __half g_vt[(size_t)Bb * NK * HD * Tt];  // half V^T [b][kh][h][t]
__device__ __half g_oh[(size_t)MROWS * NQ * HD];    // half attention output
__device__ __half g_wqkv[4096 * 2048];              // [q_w^T; k_w^T; v_w^T]
__device__ __half g_wto[2048 * 2048];               // o_w^T [D][NH]
__device__ float  g_sin[Tt * 64];
__device__ float  g_cos[Tt * 64];

__device__ __forceinline__ uint32_t pack2(float a, float b) {
    __half2 h = __floats2half2_rn(a, b);
    return *(uint32_t*)&h;
}

__device__ __forceinline__ void mma_f16(float* d, const uint32_t* a,
                                        uint32_t b0, uint32_t b1) {
    asm volatile(
        "mma.sync.aligned.m16n8k16.row.col.f32.f16.f16.f32 "
        "{%0,%1,%2,%3}, {%4,%5,%6,%7}, {%8,%9}, {%0,%1,%2,%3};"
        : "+f"(d[0]), "+f"(d[1]), "+f"(d[2]), "+f"(d[3])
        : "r"(a[0]), "r"(a[1]), "r"(a[2]), "r"(a[3]), "r"(b0), "r"(b1));
}

__device__ __forceinline__ void ldsm4h(uint32_t* r, const __half* p) {
    uint32_t a = (uint32_t)__cvta_generic_to_shared(p);
    asm volatile("ldmatrix.sync.aligned.m8n8.x4.shared.b16 {%0,%1,%2,%3}, [%4];"
                 : "=r"(r[0]), "=r"(r[1]), "=r"(r[2]), "=r"(r[3]) : "r"(a));
}

__device__ __forceinline__ void cpa16(void* dst, const void* src) {
    uint32_t d = (uint32_t)__cvta_generic_to_shared(dst);
    asm volatile("cp.async.cg.shared.global [%0], [%1], 16;" :: "r"(d), "l"(src));
}
#define CP_COMMIT asm volatile("cp.async.commit_group;")
#define CP_WAIT(n) asm volatile("cp.async.wait_group %0;" :: "n"(n))

// ---------------------------------------------------------------------------
// setup: ALL input-only preprocessing in one launch (block-range dispatch).
//  [0, 4096):         x fp32 -> half (8 elems/thread)
//  [4096, 4608):      RoPE sin/cos table
//  [4608, 12800):     fused q/k/v weight transpose -> g_wqkv
//  [12800, 16896):    o_w transpose -> g_wto
// ---------------------------------------------------------------------------
__global__ __launch_bounds__(256) void setup(const float* __restrict__ x,
                                             __half* __restrict__ xh,
                                             const float* __restrict__ qw,
                                             const float* __restrict__ kw,
                                             const float* __restrict__ vw,
                                             const float* __restrict__ ow,
                                             __half* __restrict__ wqkv,
                                             __half* __restrict__ wto) {
    __shared__ float t[32][33];
    const int bid = blockIdx.x;
    if (bid < 4096) {
        size_t i = ((size_t)bid * 256 + threadIdx.x) * 8;
        float4 a = *(const float4*)(x + i);
        float4 b = *(const float4*)(x + i + 4);
        uint4 w = make_uint4(pack2(a.x, a.y), pack2(a.z, a.w),
                             pack2(b.x, b.y), pack2(b.z, b.w));
        *(uint4*)(xh + i) = w;
    } else if (bid < 4608) {
        int idx = (bid - 4096) * 256 + threadIdx.x;
        if (idx >= Tt * 64) return;
        int tt = idx >> 6, i = idx & 63;
        double ang = (double)tt * exp(-0.21586735246819178 * (double)i);
        double s, c;
        sincos(ang, &s, &c);
        g_sin[idx] = (float)s;
        g_cos[idx] = (float)c;
    } else if (bid < 12800) {
        const int idx = bid - 4608;               // 128 x 64
        const int colg = (idx & 127) << 5;
        const int by = (idx >> 7) << 5;
        const float* src;
        int srccol, C;
        if (colg < 2048)      { src = qw; srccol = colg;        C = 2048; }
        else if (colg < 3072) { src = kw; srccol = colg - 2048; C = 1024; }
        else                  { src = vw; srccol = colg - 3072; C = 1024; }
        const int tx = threadIdx.x & 31, ty = threadIdx.x >> 5;
#pragma unroll
        for (int i = 0; i < 32; i += 8)
            t[ty + i][tx] = src[(size_t)(by + ty + i) * C + srccol + tx];
        __syncthreads();
#pragma unroll
        for (int i = 0; i < 32; i += 8)
            wqkv[(size_t)(colg + ty + i) * 2048 + by + tx] = __float2half(t[tx][ty + i]);
    } else {
        const int idx = bid - 12800;              // 64 x 64 (Dd/32, NH/32)
        const int bx = (idx & 63) << 5;           // col tile in Dd
        const int by = (idx >> 6) << 5;           // row tile in NH
        const int tx = threadIdx.x & 31, ty = threadIdx.x >> 5;
#pragma unroll
        for (int i = 0; i < 32; i += 8)
            t[ty + i][tx] = ow[(size_t)(by + ty + i) * Dd + bx + tx];
        __syncthreads();
#pragma unroll
        for (int i = 0; i < 32; i += 8)
            wto[(size_t)(bx + ty + i) * 2048 + by + tx] = __float2half(t[tx][ty + i]);
    }
}

// ---------------------------------------------------------------------------
// fp16 GEMM (round-15 proven version): 3-stage cp.async ring, one
// __syncthreads per k-iteration, __launch_bounds__(256,2).
// Block 128x128x32, 8 warps (2m x 4n).
// MODE 0: fp32 row-major out C0. MODE 1: fused QKV epilogue.
// ---------------------------------------------------------------------------
template <int MODE>
__global__ __launch_bounds__(256, 2) void gemm_h5(const __half* __restrict__ A,
                                                  const __half* __restrict__ BT,
                                                  float* __restrict__ C0,
                                                  __half* __restrict__ Qh,
                                                  __half* __restrict__ Kh,
                                                  __half* __restrict__ Vt,
                                                  const float* __restrict__ qnw,
                                                  const float* __restrict__ knw,
                                                  int M, int N, int K) {
    extern __shared__ __half sm3[];
    __half* sA = sm3;             // 3 * 5120
    __half* sB = sm3 + 3 * 5120;  // 3 * 5120

    const int tid = threadIdx.x;
    const int bm = blockIdx.y << 7, bn = blockIdx.x << 7;
    const int warp = tid >> 5, lane = tid & 31;
    const int wm = (warp >> 2) << 6, wn = (warp & 3) << 5;
    const int grp = lane >> 2, qd = lane & 3;

    const int rs = tid >> 1;
    const int cb = (tid & 1) << 4;

    const int a_row = (lane & 7) + ((lane >> 3) & 1) * 8;
    const int a_col = ((lane >> 4) & 1) * 8;
    const int b_row = (lane & 7) + ((lane >> 4) & 1) * 8;
    const int b_col = ((lane >> 3) & 1) * 8;

    float acc[4][4][4];
#pragma unroll
    for (int i = 0; i < 4; i++)
#pragma unroll
        for (int j = 0; j < 4; j++)
#pragma unroll
            for (int r = 0; r < 4; r++) acc[i][j][r] = 0.f;

    const __half* Ap = A + (size_t)(bm + rs) * K + cb;
    const __half* Bp = BT + (size_t)(bn + rs) * K + cb;
    const int soff = rs * 40 + cb;

    const int nkt = K >> 5;
#pragma unroll
    for (int s = 0; s < 2; s++) {
        const int k0 = s << 5;
        cpa16(&sA[s * 5120 + soff], Ap + k0);
        cpa16(&sA[s * 5120 + soff + 8], Ap + k0 + 8);
        cpa16(&sB[s * 5120 + soff], Bp + k0);
        cpa16(&sB[s * 5120 + soff + 8], Bp + k0 + 8);
        CP_COMMIT;
    }

    int slot = 0;
    for (int kt = 0; kt < nkt; kt++) {
        CP_WAIT(1);
        __syncthreads();
        if (kt + 2 < nkt) {
            const int k0 = (kt + 2) << 5;
            const int ns = (slot + 2 >= 3) ? slot - 1 : slot + 2;
            cpa16(&sA[ns * 5120 + soff], Ap + k0);
            cpa16(&sA[ns * 5120 + soff + 8], Ap + k0 + 8);
            cpa16(&sB[ns * 5120 + soff], Bp + k0);
            cpa16(&sB[ns * 5120 + soff + 8], Bp + k0 + 8);
        }
        CP_COMMIT;

        const __half* sAb = sA + slot * 5120;
        const __half* sBb = sB + slot * 5120;
#pragma unroll
        for (int ks = 0; ks < 2; ks++) {
            uint32_t af[4][4], bf[2][4];
#pragma unroll
            for (int mt = 0; mt < 4; mt++)
                ldsm4h(af[mt], &sAb[(wm + mt * 16 + a_row) * 40 + ks * 16 + a_col]);
#pragma unroll
            for (int np = 0; np < 2; np++)
                ldsm4h(bf[np], &sBb[(wn + np * 16 + b_row) * 40 + ks * 16 + b_col]);
#pragma unroll
            for (int mt = 0; mt < 4; mt++)
#pragma unroll
                for (int nt = 0; nt < 4; nt++)
                    mma_f16(acc[mt][nt], af[mt],
                            bf[nt >> 1][(nt & 1) * 2], bf[nt >> 1][(nt & 1) * 2 + 1]);
        }
        slot = (slot + 1 >= 3) ? 0 : slot + 1;
    }

    if (MODE == 0) {
#pragma unroll
        for (int mt = 0; mt < 4; mt++)
#pragma unroll
            for (int nt = 0; nt < 4; nt++) {
                int row = bm + wm + (mt << 4) + grp;
                int col = bn + wn + (nt << 3) + (qd << 1);
                *(float2*)(C0 + (size_t)row * N + col) =
                    make_float2(acc[mt][nt][0], acc[mt][nt][1]);
                *(float2*)(C0 + (size_t)(row + 8) * N + col) =
                    make_float2(acc[mt][nt][2], acc[mt][nt][3]);
            }
    } else if (bn >= 3072) {
#pragma unroll
        for (int mt = 0; mt < 4; mt++)
#pragma unroll
            for (int nt = 0; nt < 4; nt++) {
                int row = bm + wm + (mt << 4) + grp;
                int col = (bn - 3072) + wn + (nt << 3) + (qd << 1);
                int b = row >> 11, t = row & 2047;
                size_t base0 = ((size_t)b * NK * HD + col) * Tt + t;
                size_t base1 = ((size_t)b * NK * HD + col + 1) * Tt + t;
                Vt[base0] = __float2half(acc[mt][nt][0]);
                Vt[base1] = __float2half(acc[mt][nt][1]);
                Vt[base0 + 8] = __float2half(acc[mt][nt][2]);
                Vt[base1 + 8] = __float2half(acc[mt][nt][3]);
            }
    } else {
        // Q/K region: fused RMSNorm + RoPE via fp32 smem ytile.
        __syncthreads();
        float* yt = (float*)sm3;  // 128 x 132 fp32 = 67584 B
#pragma unroll
        for (int mt = 0; mt < 4; mt++)
#pragma unroll
            for (int nt = 0; nt < 4; nt++) {
                int row = wm + (mt << 4) + grp;
                int col = wn + (nt << 3) + (qd << 1);
                yt[row * 132 + col] = acc[mt][nt][0];
                yt[row * 132 + col + 1] = acc[mt][nt][1];
                yt[(row + 8) * 132 + col] = acc[mt][nt][2];
                yt[(row + 8) * 132 + col + 1] = acc[mt][nt][3];
            }
        __syncthreads();

        const float* wvec = (bn < 2048) ? qnw : knw;
        const int row = tid >> 1, hf = tid & 1;
        const float* yr = yt + row * 132;

        float ss = 0.f;
#pragma unroll
        for (int c = 0; c < 64; c += 4) {
            float4 v = *(const float4*)(yr + hf * 64 + c);
            ss += v.x * v.x + v.y * v.y + v.z * v.z + v.w * v.w;
        }
        ss += __shfl_xor_sync(0xffffffffu, ss, 1);
        const float rinv = rsqrtf(ss * (1.0f / (float)HD) + 1e-6f);

        const int grow = bm + row;
        const int b = grow >> 11, t = grow & 2047;
        __half* dst;
        if (bn < 2048) dst = Qh + ((size_t)(b * Tt + t) * NQ + (bn >> 7)) * HD;
        else           dst = Kh + ((size_t)(b * Tt + t) * NK + ((bn - 2048) >> 7)) * HD;
        const float* srow = g_sin + t * 64;
        const float* crow = g_cos + t * 64;

#pragma unroll
        for (int c0 = 0; c0 < 64; c0 += 4) {
            const int c = hf * 64 + c0;
            float4 yv = *(const float4*)(yr + c);
            float4 pv = *(const float4*)(yr + (c ^ 64));
            float4 wv = *(const float4*)(wvec + c);
            float4 wp = *(const float4*)(wvec + (c ^ 64));
            float4 sv = *(const float4*)(srow + c0);
            float4 cv = *(const float4*)(crow + c0);
            float y0 = wv.x * yv.x * rinv, p0 = wp.x * pv.x * rinv;
            float y1 = wv.y * yv.y * rinv, p1 = wp.y * pv.y * rinv;
            float y2 = wv.z * yv.z * rinv, p2 = wp.z * pv.z * rinv;
            float y3 = wv.w * yv.w * rinv, p3 = wp.w * pv.w * rinv;
            float o0, o1, o2, o3;
            if (hf == 0) {
                o0 = y0 * cv.x - p0 * sv.x; o1 = y1 * cv.y - p1 * sv.y;
                o2 = y2 * cv.z - p2 * sv.z; o3 = y3 * cv.w - p3 * sv.w;
            } else {
                o0 = y0 * cv.x + p0 * sv.x; o1 = y1 * cv.y + p1 * sv.y;
                o2 = y2 * cv.z + p2 * sv.z; o3 = y3 * cv.w + p3 * sv.w;
            }
            *(uint2*)(dst + c) = make_uint2(pack2(o0, o1), pack2(o2, o3));
        }
    }
}

// ---------------------------------------------------------------------------
// Flash attention fp16 mma.sync, s-tile 64, cp.async double-buffered K/V.
// LPT: largest q-tiles launch first (qt reversed vs blockIdx.x).
// ---------------------------------------------------------------------------
__global__ __launch_bounds__(256) void flash_h2(const __half* __restrict__ Q,
                                                const __half* __restrict__ Kc,
                                                const __half* __restrict__ VT,
                                                __half* __restrict__ O) {
    extern __shared__ __half smh[];
    __half* sK = smh;                  // 2 * 8704
    __half* sVT = sK + 2 * 8704;       // 2 * 9216
    __half* sP = sVT + 2 * 9216;       // 8 * 1152

    const int tid = threadIdx.x;
    const int w = tid >> 5, lane = tid & 31;
    const int grp = lane >> 2, qd = lane & 3;
    const int b = blockIdx.z, n = blockIdx.y;
    const int qt = (gridDim.x - 1 - blockIdx.x) << 7;   // LPT: big tiles first
    const int kh = n >> 1;

    const int a_row = (lane & 7) + ((lane >> 3) & 1) * 8;
    const int a_col = ((lane >> 4) & 1) * 8;
    const int b_row = (lane & 7) + ((lane >> 4) & 1) * 8;
    const int b_col = ((lane >> 3) & 1) * 8;

    uint32_t qf[8][4];
    {
        const __half* Qb = Q + ((size_t)(b * Tt + qt) * NQ + n) * HD;
#pragma unroll
        for (int c = 0; c < 2; c++) {
            __half* sKc = sK + c * 8704;
#pragma unroll
            for (int u = 0; u < 4; u++) {
                int cc = tid + (u << 8);
                int r = cc >> 4, ch = (cc & 15) << 3;
                *(uint4*)&sKc[r * 136 + ch] =
                    *(const uint4*)(Qb + (size_t)(c * 64 + r) * (NQ * HD) + ch);
            }
            __syncthreads();
            if ((w >> 2) == c) {
                const int lr = ((w & 3) << 4) + a_row;
#pragma unroll
                for (int kp = 0; kp < 8; kp++)
                    ldsm4h(qf[kp], &sKc[lr * 136 + (kp << 4) + a_col]);
            }
            __syncthreads();
        }
    }

    float oacc[16][4];
#pragma unroll
    for (int i = 0; i < 16; i++)
#pragma unroll
        for (int j = 0; j < 4; j++) oacc[i][j] = 0.f;
    float m0 = -1e30f, m1 = -1e30f, l0 = 0.f, l1 = 0.f;

    const float scale = 0.08838834764831845f;
    const int row0 = qt + (w << 4) + grp;
    const int row1 = row0 + 8;
    const int wmax = qt + (w << 4) + 15;
    const int ntile = (qt >> 6) + 2;
    __half* sPw = sP + w * 1152;

    const __half* Kbase = Kc + ((size_t)b * Tt * NK + kh) * HD;
    const __half* Vbase = VT + ((size_t)(b * NK + kh) * HD) * Tt;

    auto stage = [&](int st, int buf) {
        const __half* Kb = Kbase + (size_t)(st << 6) * (NK * HD);
        const __half* Vb = Vbase + (st << 6);
        __half* dK = sK + buf * 8704;
        __half* dV = sVT + buf * 9216;
#pragma unroll
        for (int u = 0; u < 4; u++) {
            int cc = tid + (u << 8);
            int r = cc >> 4, ch = (cc & 15) << 3;
            cpa16(&dK[r * 136 + ch], Kb + (size_t)r * (NK * HD) + ch);
            int rv = cc >> 3, cv = (cc & 7) << 3;
            cpa16(&dV[rv * 72 + cv], Vb + (size_t)rv * Tt + cv);
        }
    };

    stage(0, 0);
    CP_COMMIT;

    for (int st = 0; st < ntile; st++) {
        const int s0 = st << 6;
        const int buf = st & 1;
        if (st + 1 < ntile) {
            stage(st + 1, buf ^ 1);
            CP_COMMIT;
            CP_WAIT(1);
        } else {
            CP_WAIT(0);
        }
        __syncthreads();

        if (s0 <= wmax) {
            const __half* sKb = sK + buf * 8704;
            const __half* sVb = sVT + buf * 9216;

            float sacc[8][4];
#pragma unroll
            for (int i = 0; i < 8; i++)
#pragma unroll
                for (int j = 0; j < 4; j++) sacc[i][j] = 0.f;
#pragma unroll
            for (int kp = 0; kp < 8; kp++) {
#pragma unroll
                for (int np = 0; np < 4; np++) {
                    uint32_t bf[4];
                    ldsm4h(bf, &sKb[(np * 16 + b_row) * 136 + (kp << 4) + b_col]);
                    mma_f16(sacc[np * 2], qf[kp], bf[0], bf[1]);
                    mma_f16(sacc[np * 2 + 1], qf[kp], bf[2], bf[3]);
                }
            }

            float mx0 = -1e30f, mx1 = -1e30f;
#pragma unroll
            for (int nt = 0; nt < 8; nt++) {
                int colb = s0 + (nt << 3) + (qd << 1);
                float v0 = sacc[nt][0] * scale;
                float v1 = sacc[nt][1] * scale;
                float v2 = sacc[nt][2] * scale;
                float v3 = sacc[nt][3] * scale;
                if (colb > row0)     v0 = -1e30f;
                if (colb + 1 > row0) v1 = -1e30f;
                if (colb > row1)     v2 = -1e30f;
                if (colb + 1 > row1) v3 = -1e30f;
                sacc[nt][0] = v0; sacc[nt][1] = v1; sacc[nt][2] = v2; sacc[nt][3] = v3;
                mx0 = fmaxf(mx0, fmaxf(v0, v1));
                mx1 = fmaxf(mx1, fmaxf(v2, v3));
            }
            mx0 = fmaxf(mx0, __shfl_xor_sync(0xffffffffu, mx0, 1));
            mx0 = fmaxf(mx0, __shfl_xor_sync(0xffffffffu, mx0, 2));
            mx1 = fmaxf(mx1, __shfl_xor_sync(0xffffffffu, mx1, 1));
            mx1 = fmaxf(mx1, __shfl_xor_sync(0xffffffffu, mx1, 2));
            float mn0 = fmaxf(m0, mx0), mn1 = fmaxf(m1, mx1);
            float a0 = __expf(m0 - mn0), a1 = __expf(m1 - mn1);
            m0 = mn0; m1 = mn1;
            float ps0 = 0.f, ps1 = 0.f;
#pragma unroll
            for (int nt = 0; nt < 8; nt++) {
                float p0 = __expf(sacc[nt][0] - m0);
                float p1 = __expf(sacc[nt][1] - m0);
                float p2 = __expf(sacc[nt][2] - m1);
                float p3 = __expf(sacc[nt][3] - m1);
                ps0 += p0 + p1; ps1 += p2 + p3;
                int col = (nt << 3) + (qd << 1);
                *(uint32_t*)&sPw[grp * 72 + col] = pack2(p0, p1);
                *(uint32_t*)&sPw[(grp + 8) * 72 + col] = pack2(p2, p3);
            }
            ps0 += __shfl_xor_sync(0xffffffffu, ps0, 1);
            ps0 += __shfl_xor_sync(0xffffffffu, ps0, 2);
            ps1 += __shfl_xor_sync(0xffffffffu, ps1, 1);
            ps1 += __shfl_xor_sync(0xffffffffu, ps1, 2);
            l0 = l0 * a0 + ps0;
            l1 = l1 * a1 + ps1;
#pragma unroll
            for (int nt = 0; nt < 16; nt++) {
                oacc[nt][0] *= a0; oacc[nt][1] *= a0;
                oacc[nt][2] *= a1; oacc[nt][3] *= a1;
            }
            __syncwarp();

#pragma unroll
            for (int kp = 0; kp < 4; kp++) {
                uint32_t af[4];
                ldsm4h(af, &sPw[a_row * 72 + (kp << 4) + a_col]);
#pragma unroll
                for (int np = 0; np < 8; np++) {
                    uint32_t bf[4];
                    ldsm4h(bf, &sVb[(np * 16 + b_row) * 72 + (kp << 4) + b_col]);
                    mma_f16(oacc[np * 2], af, bf[0], bf[1]);
                    mma_f16(oacc[np * 2 + 1], af, bf[2], bf[3]);
                }
            }
        }
        __syncthreads();
    }

    const float i0 = 1.0f / l0, i1 = 1.0f / l1;
    __half* Ob0 = O + ((size_t)(b * Tt + row0) * NQ + n) * HD;
    __half* Ob1 = O + ((size_t)(b * Tt + row1) * NQ + n) * HD;
#pragma unroll
    for (int nt = 0; nt < 16; nt++) {
        int col = (nt << 3) + (qd << 1);
        *(uint32_t*)(Ob0 + col) = pack2(oacc[nt][0] * i0, oacc[nt][1] * i0);
        *(uint32_t*)(Ob1 + col) = pack2(oacc[nt][2] * i1, oacc[nt][3] * i1);
    }
}

// ---------------------------------------------------------------------------
// Launch: 1 setup, 2 QKV gemm (fused rms/rope/V^T), 3 flash, 4 O-proj gemm
// ---------------------------------------------------------------------------
extern "C" void kernel_launch(void* const* d_in, const int* in_sizes, int n_in,
                              void* d_out, int out_size) {
    (void)in_sizes; (void)n_in; (void)out_size;
    const float* x   = (const float*)d_in[0];
    const float* qw  = (const float*)d_in[1];
    const float* kw  = (const float*)d_in[2];
    const float* vw  = (const float*)d_in[3];
    const float* ow  = (const float*)d_in[4];
    const float* qnw = (const float*)d_in[5];
    const float* knw = (const float*)d_in[6];
    float* out = (float*)d_out;

    __half *gxh, *gqh, *gkh, *gvt, *goh, *wqkv, *wto;
    cudaGetSymbolAddress((void**)&gxh, g_xh);
    cudaGetSymbolAddress((void**)&gqh, g_qh);
    cudaGetSymbolAddress((void**)&gkh, g_kh);
    cudaGetSymbolAddress((void**)&gvt, g_vt);
    cudaGetSymbolAddress((void**)&goh, g_oh);
    cudaGetSymbolAddress((void**)&wqkv, g_wqkv);
    cudaGetSymbolAddress((void**)&wto, g_wto);

    const int M = MROWS;     // 4096

    cudaFuncSetAttribute(gemm_h5<0>, cudaFuncAttributeMaxDynamicSharedMemorySize, 61440);
    cudaFuncSetAttribute(gemm_h5<1>, cudaFuncAttributeMaxDynamicSharedMemorySize, 67584);

    // 1: all preprocessing
    setup<<<16896, 256>>>(x, gxh, qw, kw, vw, ow, wqkv, wto);
    // 2: fused QKV projection + rms + rope + V-transpose
    gemm_h5<1><<<dim3(32, 32), 256, 67584>>>(gxh, wqkv, nullptr, gqh, gkh, gvt,
                                             qnw, knw, M, 4096, Dd);
    // 3: flash attention (LPT-ordered)
    size_t fsmem = (size_t)(2 * 8704 + 2 * 9216 + 8 * 1152) * sizeof(__half); // 90112
    cudaFuncSetAttribute(flash_h2, cudaFuncAttributeMaxDynamicSharedMemorySize, (int)fsmem);
    flash_h2<<<dim3(Tt / 128, NQ, Bb), 256, fsmem>>>(gqh, gkh, gvt, goh);
    // 4: output projection
    gemm_h5<0><<<dim3(Dd / 128, M / 128), 256, 61440>>>(goh, wto, out, nullptr, nullptr,
                                                        nullptr, nullptr, nullptr, M, Dd, Dd);
}